// round 1
// baseline (speedup 1.0000x reference)
#include <cuda_runtime.h>

#define NN 20000   // nodes
#define NR 200     // relations
#define D  128     // dim
#define NE 200000  // edges
#define NT 8       // timesteps

// Scratch (static __device__ arrays: no allocation at runtime)
__device__ float g_agg[(size_t)NT * NN * D];   // 82 MB: per-time aggregated messages
__device__ float g_H[(size_t)NN * D];          // tanh(agg @ W_enc) for current step
__device__ float g_zpre[(size_t)NN * D];       // z pre-activation for current step
__device__ float g_state[(size_t)NN * D];      // recurrent state

// ---------------------------------------------------------------------------
// Zero agg + state
// ---------------------------------------------------------------------------
__global__ void zero_kernel() {
    const size_t na = (size_t)NT * NN * D / 4;
    const size_t ns = (size_t)NN * D / 4;
    float4 z = make_float4(0.f, 0.f, 0.f, 0.f);
    for (size_t i = (size_t)blockIdx.x * blockDim.x + threadIdx.x; i < na + ns;
         i += (size_t)gridDim.x * blockDim.x) {
        if (i < na) reinterpret_cast<float4*>(g_agg)[i] = z;
        else        reinterpret_cast<float4*>(g_state)[i - na] = z;
    }
}

// ---------------------------------------------------------------------------
// One-pass edge scatter: agg[t][dst] += node_emb[src] * rel_emb[type] * w
// One warp per edge; each lane handles 4 contiguous dims.
// ---------------------------------------------------------------------------
__global__ void scatter_kernel(const int* __restrict__ src, const int* __restrict__ dst,
                               const int* __restrict__ etype, const int* __restrict__ etime,
                               const float* __restrict__ ew,
                               const float* __restrict__ node_emb,
                               const float* __restrict__ rel_emb) {
    int gid  = blockIdx.x * blockDim.x + threadIdx.x;
    int e    = gid >> 5;
    int lane = gid & 31;
    if (e >= NE) return;
    int t = etime[e];
    if ((unsigned)t >= NT) return;
    int s = src[e], d = dst[e], r = etype[e];
    float w = ew[e];
    float4 a = reinterpret_cast<const float4*>(node_emb + (size_t)s * D)[lane];
    float4 b = reinterpret_cast<const float4*>(rel_emb  + (size_t)r * D)[lane];
    float* o = g_agg + ((size_t)t * NN + d) * D + lane * 4;
    atomicAdd(o + 0, a.x * b.x * w);
    atomicAdd(o + 1, a.y * b.y * w);
    atomicAdd(o + 2, a.z * b.z * w);
    atomicAdd(o + 3, a.w * b.w * w);
}

// ---------------------------------------------------------------------------
// H = tanh(agg_t @ W_enc)   [20000,128] x [128,128]
// Block: 256 threads, 32 rows. Thread (ty=tid/32, tx=tid%32) computes
// rows ty*4..ty*4+3, cols tx*4..tx*4+3 (4x4 register accumulators).
// Shared: W (64KB) + X tile (16KB).
// ---------------------------------------------------------------------------
#define HENC_SMEM ((D * D + 32 * D) * 4)

__global__ void henc_kernel(int t, const float* __restrict__ Wenc) {
    extern __shared__ float sm[];
    float* Ws = sm;           // [128][128]
    float* Xs = sm + D * D;   // [32][128]
    int tid = threadIdx.x;
    int tx  = tid & 31;
    int ty  = tid >> 5;
    int row0 = blockIdx.x * 32;

    for (int i = tid; i < D * D / 4; i += blockDim.x)
        reinterpret_cast<float4*>(Ws)[i] = reinterpret_cast<const float4*>(Wenc)[i];
    const float* A = g_agg + ((size_t)t * NN + row0) * D;
    for (int i = tid; i < 32 * D / 4; i += blockDim.x)
        reinterpret_cast<float4*>(Xs)[i] = reinterpret_cast<const float4*>(A)[i];
    __syncthreads();

    float acc[4][4];
#pragma unroll
    for (int r = 0; r < 4; r++)
#pragma unroll
        for (int c = 0; c < 4; c++) acc[r][c] = 0.f;

#pragma unroll 4
    for (int k = 0; k < D; k++) {
        float4 wv = *reinterpret_cast<float4*>(&Ws[k * D + tx * 4]);
#pragma unroll
        for (int r = 0; r < 4; r++) {
            float xv = Xs[(ty * 4 + r) * D + k];
            acc[r][0] += xv * wv.x;
            acc[r][1] += xv * wv.y;
            acc[r][2] += xv * wv.z;
            acc[r][3] += xv * wv.w;
        }
    }

    float* Hout = g_H + (size_t)row0 * D;
#pragma unroll
    for (int r = 0; r < 4; r++) {
        float4 v = make_float4(tanhf(acc[r][0]), tanhf(acc[r][1]),
                               tanhf(acc[r][2]), tanhf(acc[r][3]));
        *reinterpret_cast<float4*>(&Hout[(ty * 4 + r) * D + tx * 4]) = v;
    }
}

// ---------------------------------------------------------------------------
// Gate GEMMs: X = [H | state] (K=256), B = [Wtop ; Ubot] (256x128).
// gatez: zpre = X @ [Wz;Uz]               (stored raw)
// gateh: candpre = X @ [Wh;Uh], then fused state update:
//        z = sigmoid(zpre+bz), cand = tanh(candpre+bh)
//        new_state = (1-z)*state + z*cand
// Shared: B (128KB) + X tile (32KB).
// ---------------------------------------------------------------------------
#define GATE_SMEM ((2 * D * D + 32 * 2 * D) * 4)

__device__ __forceinline__ void load_gate_tiles(float* Ws, float* Xs,
                                                const float* __restrict__ Wtop,
                                                const float* __restrict__ Ubot,
                                                int row0, int tid, int nthreads) {
    for (int i = tid; i < D * D / 4; i += nthreads) {
        reinterpret_cast<float4*>(Ws)[i]         = reinterpret_cast<const float4*>(Wtop)[i];
        reinterpret_cast<float4*>(Ws + D * D)[i] = reinterpret_cast<const float4*>(Ubot)[i];
    }
    for (int i = tid; i < 32 * D / 4; i += nthreads) {
        int r  = i >> 5;        // row in tile (D/4 = 32 float4 per half-row)
        int kk = i & 31;
        reinterpret_cast<float4*>(Xs + r * 2 * D)[kk] =
            reinterpret_cast<const float4*>(g_H + (size_t)(row0 + r) * D)[kk];
        reinterpret_cast<float4*>(Xs + r * 2 * D + D)[kk] =
            reinterpret_cast<const float4*>(g_state + (size_t)(row0 + r) * D)[kk];
    }
}

__device__ __forceinline__ void gate_mma(const float* Ws, const float* Xs,
                                         int tx, int ty, float acc[4][4]) {
#pragma unroll
    for (int r = 0; r < 4; r++)
#pragma unroll
        for (int c = 0; c < 4; c++) acc[r][c] = 0.f;
#pragma unroll 4
    for (int k = 0; k < 2 * D; k++) {
        float4 wv = *reinterpret_cast<const float4*>(&Ws[k * D + tx * 4]);
#pragma unroll
        for (int r = 0; r < 4; r++) {
            float xv = Xs[(ty * 4 + r) * 2 * D + k];
            acc[r][0] += xv * wv.x;
            acc[r][1] += xv * wv.y;
            acc[r][2] += xv * wv.z;
            acc[r][3] += xv * wv.w;
        }
    }
}

__global__ void gatez_kernel(const float* __restrict__ Wz, const float* __restrict__ Uz) {
    extern __shared__ float sm[];
    float* Ws = sm;
    float* Xs = sm + 2 * D * D;
    int tid = threadIdx.x, tx = tid & 31, ty = tid >> 5;
    int row0 = blockIdx.x * 32;
    load_gate_tiles(Ws, Xs, Wz, Uz, row0, tid, blockDim.x);
    __syncthreads();
    float acc[4][4];
    gate_mma(Ws, Xs, tx, ty, acc);
#pragma unroll
    for (int r = 0; r < 4; r++) {
        float4 v = make_float4(acc[r][0], acc[r][1], acc[r][2], acc[r][3]);
        *reinterpret_cast<float4*>(&g_zpre[(size_t)(row0 + ty * 4 + r) * D + tx * 4]) = v;
    }
}

__device__ __forceinline__ float sigmoidf_(float x) { return 1.f / (1.f + expf(-x)); }

__global__ void gateh_kernel(const float* __restrict__ Wh, const float* __restrict__ Uh,
                             const float* __restrict__ bz, const float* __restrict__ bh,
                             float* outp) {
    extern __shared__ float sm[];
    float* Ws = sm;
    float* Xs = sm + 2 * D * D;
    int tid = threadIdx.x, tx = tid & 31, ty = tid >> 5;
    int row0 = blockIdx.x * 32;
    load_gate_tiles(Ws, Xs, Wh, Uh, row0, tid, blockDim.x);
    __syncthreads();
    float acc[4][4];
    gate_mma(Ws, Xs, tx, ty, acc);

    float* out = outp ? outp : g_state;
    float4 bzv = *reinterpret_cast<const float4*>(&bz[tx * 4]);
    float4 bhv = *reinterpret_cast<const float4*>(&bh[tx * 4]);
#pragma unroll
    for (int r = 0; r < 4; r++) {
        int row = row0 + ty * 4 + r;
        float4 zp = *reinterpret_cast<float4*>(&g_zpre[(size_t)row * D + tx * 4]);
        float4 st = *reinterpret_cast<float4*>(&Xs[(ty * 4 + r) * 2 * D + D + tx * 4]);
        float z0 = sigmoidf_(zp.x + bzv.x), z1 = sigmoidf_(zp.y + bzv.y);
        float z2 = sigmoidf_(zp.z + bzv.z), z3 = sigmoidf_(zp.w + bzv.w);
        float c0 = tanhf(acc[r][0] + bhv.x), c1 = tanhf(acc[r][1] + bhv.y);
        float c2 = tanhf(acc[r][2] + bhv.z), c3 = tanhf(acc[r][3] + bhv.w);
        float4 v = make_float4((1.f - z0) * st.x + z0 * c0,
                               (1.f - z1) * st.y + z1 * c1,
                               (1.f - z2) * st.z + z2 * c2,
                               (1.f - z3) * st.w + z3 * c3);
        *reinterpret_cast<float4*>(&out[(size_t)row * D + tx * 4]) = v;
    }
}

// ---------------------------------------------------------------------------
extern "C" void kernel_launch(void* const* d_in, const int* in_sizes, int n_in,
                              void* d_out, int out_size) {
    const int*   ei       = (const int*)d_in[0];
    const int*   src      = ei;
    const int*   dst      = ei + NE;
    const int*   etype    = (const int*)d_in[1];
    const int*   etime    = (const int*)d_in[2];
    const float* ew       = (const float*)d_in[3];
    const float* node_emb = (const float*)d_in[4];
    const float* rel_emb  = (const float*)d_in[5];
    const float* Wenc     = (const float*)d_in[6];
    const float* Wz       = (const float*)d_in[7];
    const float* Uz       = (const float*)d_in[8];
    const float* Wh       = (const float*)d_in[9];
    const float* Uh       = (const float*)d_in[10];
    const float* bz       = (const float*)d_in[11];
    const float* bh       = (const float*)d_in[12];

    cudaFuncSetAttribute(henc_kernel,  cudaFuncAttributeMaxDynamicSharedMemorySize, HENC_SMEM);
    cudaFuncSetAttribute(gatez_kernel, cudaFuncAttributeMaxDynamicSharedMemorySize, GATE_SMEM);
    cudaFuncSetAttribute(gateh_kernel, cudaFuncAttributeMaxDynamicSharedMemorySize, GATE_SMEM);

    zero_kernel<<<2048, 256>>>();
    scatter_kernel<<<(NE * 32 + 255) / 256, 256>>>(src, dst, etype, etime, ew,
                                                   node_emb, rel_emb);

    const int nblocks = NN / 32;  // 625
    for (int t = 0; t < NT; t++) {
        henc_kernel<<<nblocks, 256, HENC_SMEM>>>(t, Wenc);
        gatez_kernel<<<nblocks, 256, GATE_SMEM>>>(Wz, Uz);
        gateh_kernel<<<nblocks, 256, GATE_SMEM>>>(Wh, Uh, bz, bh,
                                                  (t == NT - 1) ? (float*)d_out : nullptr);
    }
}

// round 3
// speedup vs baseline: 1.6694x; 1.6694x over previous
#include <cuda_runtime.h>
#include <cuda_bf16.h>
#include <cstdint>

#define NN 20000   // nodes
#define D  128     // dim
#define NE 200000  // edges
#define NT 8       // timesteps
#define NTILES 157 // ceil(NN/128)
#define PAD 136    // bf16 elements per smem row (272B stride: conflict-free ldmatrix)

// Static device scratch (no runtime allocation)
__device__ float g_agg[(size_t)NT * NN * D];     // 82 MB per-time aggregated messages
__device__ float g_state[(size_t)NN * D];        // recurrent state
__device__ uint4 g_Wp[5 * 2 * 128 * 16];         // [w][hi/lo][n=128][k=128] bf16, transposed+split

// Dynamic smem layout (bytes): 4 X buffers + 1 W buffer, each [128][PAD] bf16
#define XA_HI 0
#define XA_LO 34816
#define XS_HI 69632
#define XS_LO 104448
#define W_HI  139264
#define W_LO  174080
#define SMEM_BYTES 208896

// ---------------------------------------------------------------------------
__device__ __forceinline__ uint32_t smem_u32(const void* p) {
    uint32_t a;
    asm("{ .reg .u64 t; cvta.to.shared.u64 t, %1; cvt.u32.u64 %0, t; }" : "=r"(a) : "l"(p));
    return a;
}

#define LDSM4(R, a) \
    asm volatile("ldmatrix.sync.aligned.m8n8.x4.shared.b16 {%0,%1,%2,%3}, [%4];" \
                 : "=r"((R)[0]), "=r"((R)[1]), "=r"((R)[2]), "=r"((R)[3]) : "r"(a))

#define MMA16816(d, a, b0, b1) \
    asm volatile("mma.sync.aligned.m16n8k16.row.col.f32.bf16.bf16.f32 " \
                 "{%0,%1,%2,%3},{%4,%5,%6,%7},{%8,%9},{%0,%1,%2,%3};" \
                 : "+f"((d)[0]), "+f"((d)[1]), "+f"((d)[2]), "+f"((d)[3]) \
                 : "r"((a)[0]), "r"((a)[1]), "r"((a)[2]), "r"((a)[3]), "r"(b0), "r"(b1))

// bf16 hi/lo split of two floats -> packed bf16x2 words (low half = first elem)
__device__ __forceinline__ void split2(float x, float y, uint32_t& h, uint32_t& l) {
    __nv_bfloat16 hx = __float2bfloat16(x), hy = __float2bfloat16(y);
    float rx = x - __bfloat162float(hx);
    float ry = y - __bfloat162float(hy);
    __nv_bfloat16 lx = __float2bfloat16(rx), ly = __float2bfloat16(ry);
    h = (uint32_t)__bfloat16_as_ushort(hx) | ((uint32_t)__bfloat16_as_ushort(hy) << 16);
    l = (uint32_t)__bfloat16_as_ushort(lx) | ((uint32_t)__bfloat16_as_ushort(ly) << 16);
}

// Convert 64 fp32 -> bf16 hi/lo into padded smem row
__device__ __forceinline__ void cvt64(char* hi, char* lo, int row, int col0,
                                      const float* __restrict__ src, bool valid) {
#pragma unroll
    for (int g = 0; g < 8; g++) {
        float4 a = make_float4(0.f, 0.f, 0.f, 0.f), b = a;
        if (valid) { a = ((const float4*)src)[g * 2]; b = ((const float4*)src)[g * 2 + 1]; }
        uint32_t h0, h1, h2, h3, l0, l1, l2, l3;
        split2(a.x, a.y, h0, l0);
        split2(a.z, a.w, h1, l1);
        split2(b.x, b.y, h2, l2);
        split2(b.z, b.w, h3, l3);
        uint32_t off = (uint32_t)(row * PAD + col0 + g * 8) * 2;
        *(uint4*)(hi + off) = make_uint4(h0, h1, h2, h3);
        *(uint4*)(lo + off) = make_uint4(l0, l1, l2, l3);
    }
}

// Copy pre-split weight w into the smem W buffer (hi+lo, padded rows)
__device__ __forceinline__ void copy_w(char* sm, int w, int tid) {
    const uint4* s = g_Wp + (size_t)w * 4096;
#pragma unroll
    for (int i = tid; i < 4096; i += 256) {
        int sp = i >> 11, j = i & 2047, n = j >> 4, kk = j & 15;
        *(uint4*)(sm + (sp ? W_LO : W_HI) + (uint32_t)(n * PAD + kk * 8) * 2) = s[i];
    }
}

// K=128 GEMM pass with bf16x3 split: acc += Xsplit @ Wsplit^T
// Warp tile 32(m) x 64(n); A row-major [m][k], B as [n][k] (mma row.col).
__device__ __forceinline__ void gemm_k128(float (&acc)[2][8][4],
                                          uint32_t xhi, uint32_t xlo,
                                          uint32_t whi, uint32_t wlo,
                                          int lane, int wm, int wn) {
    const int arow = wm * 32 + (lane & 15);
    const int acolo = (lane >> 4) * 8;
    const int brow = wn * 64 + (lane & 7) + ((lane >> 4) & 1) * 8;
    const int bcolo = ((lane >> 3) & 1) * 8;
#pragma unroll 1
    for (int ks = 0; ks < 8; ks++) {
        uint32_t Ah[2][4], Al[2][4], Bh[4][4], Bl[4][4];
        int ac = ks * 16 + acolo;
        int bc = ks * 16 + bcolo;
#pragma unroll
        for (int tm = 0; tm < 2; tm++) {
            uint32_t ao = (uint32_t)((arow + tm * 16) * PAD + ac) * 2;
            LDSM4(Ah[tm], xhi + ao);
            LDSM4(Al[tm], xlo + ao);
        }
#pragma unroll
        for (int g = 0; g < 4; g++) {
            uint32_t bo = (uint32_t)((brow + g * 16) * PAD + bc) * 2;
            LDSM4(Bh[g], whi + bo);
            LDSM4(Bl[g], wlo + bo);
        }
#pragma unroll
        for (int tm = 0; tm < 2; tm++)
#pragma unroll
            for (int tn = 0; tn < 8; tn++) {
                int g = tn >> 1, o = (tn & 1) * 2;
                MMA16816(acc[tm][tn], Ah[tm], Bh[g][o], Bh[g][o + 1]);
            }
#pragma unroll
        for (int tm = 0; tm < 2; tm++)
#pragma unroll
            for (int tn = 0; tn < 8; tn++) {
                int g = tn >> 1, o = (tn & 1) * 2;
                MMA16816(acc[tm][tn], Ah[tm], Bl[g][o], Bl[g][o + 1]);
            }
#pragma unroll
        for (int tm = 0; tm < 2; tm++)
#pragma unroll
            for (int tn = 0; tn < 8; tn++) {
                int g = tn >> 1, o = (tn & 1) * 2;
                MMA16816(acc[tm][tn], Al[tm], Bh[g][o], Bh[g][o + 1]);
            }
    }
}

// ---------------------------------------------------------------------------
// Weight prep: g_Wp[w][sp][n][k] = split(W[k][n])
// ---------------------------------------------------------------------------
__global__ void prep_weights(const float* W0, const float* W1, const float* W2,
                             const float* W3, const float* W4) {
    int idx = blockIdx.x * blockDim.x + threadIdx.x;
    if (idx >= 5 * 128 * 128) return;
    int w = idx >> 14, rem = idx & 16383, n = rem >> 7, k = rem & 127;
    const float* Ws = (w == 0) ? W0 : (w == 1) ? W1 : (w == 2) ? W2 : (w == 3) ? W3 : W4;
    float v = Ws[k * 128 + n];
    __nv_bfloat16 hv = __float2bfloat16(v);
    float res = v - __bfloat162float(hv);
    __nv_bfloat16 lv = __float2bfloat16(res);
    unsigned short* base = (unsigned short*)g_Wp;
    base[(size_t)((w * 2 + 0) * 128 + n) * 128 + k] = __bfloat16_as_ushort(hv);
    base[(size_t)((w * 2 + 1) * 128 + n) * 128 + k] = __bfloat16_as_ushort(lv);
}

// ---------------------------------------------------------------------------
__global__ void zero_kernel() {
    const size_t na = (size_t)NT * NN * D / 4;
    const size_t ns = (size_t)NN * D / 4;
    float4 z = make_float4(0.f, 0.f, 0.f, 0.f);
    for (size_t i = (size_t)blockIdx.x * blockDim.x + threadIdx.x; i < na + ns;
         i += (size_t)gridDim.x * blockDim.x) {
        if (i < na) reinterpret_cast<float4*>(g_agg)[i] = z;
        else        reinterpret_cast<float4*>(g_state)[i - na] = z;
    }
}

// ---------------------------------------------------------------------------
// Edge scatter: one warp per edge, vector reductions (red.add.v4.f32)
// ---------------------------------------------------------------------------
__global__ void scatter_kernel(const int* __restrict__ src, const int* __restrict__ dst,
                               const int* __restrict__ etype, const int* __restrict__ etime,
                               const float* __restrict__ ew,
                               const float* __restrict__ node_emb,
                               const float* __restrict__ rel_emb) {
    int gid  = blockIdx.x * blockDim.x + threadIdx.x;
    int e    = gid >> 5;
    int lane = gid & 31;
    if (e >= NE) return;
    int t = etime[e];
    if ((unsigned)t >= NT) return;
    int s = src[e], d = dst[e], r = etype[e];
    float w = ew[e];
    float4 a = reinterpret_cast<const float4*>(node_emb + (size_t)s * D)[lane];
    float4 b = reinterpret_cast<const float4*>(rel_emb  + (size_t)r * D)[lane];
    float* o = g_agg + ((size_t)t * NN + d) * D + lane * 4;
    asm volatile("red.global.add.v4.f32 [%0], {%1,%2,%3,%4};"
                 :: "l"(o), "f"(a.x * b.x * w), "f"(a.y * b.y * w),
                    "f"(a.z * b.z * w), "f"(a.w * b.w * w) : "memory");
}

// ---------------------------------------------------------------------------
// Fused per-timestep kernel (HMMA bf16x3):
//   h = tanh(agg @ Wenc); z = sig(h@Wz + s@Uz + bz); c = tanh(h@Wh + s@Uh + bh)
//   s' = (1-z)s + z c
// ---------------------------------------------------------------------------
__global__ void __launch_bounds__(256, 1) step_kernel(int t, const float* __restrict__ bz,
                                                      const float* __restrict__ bh,
                                                      float* outp) {
    extern __shared__ char sm[];
    uint32_t sb = smem_u32(sm);
    int tid = threadIdx.x, lane = tid & 31, wid = tid >> 5;
    int wm = wid & 3, wn = wid >> 2;
    int row0 = blockIdx.x * 128;

    // Phase 0: split agg + state into smem; stage Wenc
    {
        int row = tid >> 1, half = tid & 1;
        int grow = row0 + row;
        bool v = grow < NN;
        const float* pa = g_agg + ((size_t)t * NN + (v ? grow : 0)) * D + half * 64;
        const float* ps = g_state + (size_t)(v ? grow : 0) * D + half * 64;
        cvt64(sm + XA_HI, sm + XA_LO, row, half * 64, pa, v);
        cvt64(sm + XS_HI, sm + XS_LO, row, half * 64, ps, v);
    }
    copy_w(sm, 0, tid);
    __syncthreads();

    // Encoder GEMM
    float accE[2][8][4];
#pragma unroll
    for (int i = 0; i < 2; i++)
#pragma unroll
        for (int j = 0; j < 8; j++)
#pragma unroll
            for (int q = 0; q < 4; q++) accE[i][j][q] = 0.f;
    gemm_k128(accE, sb + XA_HI, sb + XA_LO, sb + W_HI, sb + W_LO, lane, wm, wn);
    __syncthreads();

    // tanh + split H back into XA buffers; stage Wz in parallel
#pragma unroll
    for (int tm = 0; tm < 2; tm++)
#pragma unroll
        for (int tn = 0; tn < 8; tn++) {
            int col = wn * 64 + tn * 8 + (lane & 3) * 2;
            int r0l = wm * 32 + tm * 16 + (lane >> 2);
            uint32_t h, l;
            split2(tanhf(accE[tm][tn][0]), tanhf(accE[tm][tn][1]), h, l);
            uint32_t off = (uint32_t)(r0l * PAD + col) * 2;
            *(uint32_t*)(sm + XA_HI + off) = h;
            *(uint32_t*)(sm + XA_LO + off) = l;
            split2(tanhf(accE[tm][tn][2]), tanhf(accE[tm][tn][3]), h, l);
            off = (uint32_t)((r0l + 8) * PAD + col) * 2;
            *(uint32_t*)(sm + XA_HI + off) = h;
            *(uint32_t*)(sm + XA_LO + off) = l;
        }
    copy_w(sm, 1, tid);
    __syncthreads();

    // z pre-activation: H@Wz + state@Uz
    float accZ[2][8][4];
#pragma unroll
    for (int i = 0; i < 2; i++)
#pragma unroll
        for (int j = 0; j < 8; j++)
#pragma unroll
            for (int q = 0; q < 4; q++) accZ[i][j][q] = 0.f;
    gemm_k128(accZ, sb + XA_HI, sb + XA_LO, sb + W_HI, sb + W_LO, lane, wm, wn);
    __syncthreads();
    copy_w(sm, 2, tid);
    __syncthreads();
    gemm_k128(accZ, sb + XS_HI, sb + XS_LO, sb + W_HI, sb + W_LO, lane, wm, wn);
    __syncthreads();

    // candidate pre-activation: H@Wh + state@Uh
    copy_w(sm, 3, tid);
    __syncthreads();
    float accH[2][8][4];
#pragma unroll
    for (int i = 0; i < 2; i++)
#pragma unroll
        for (int j = 0; j < 8; j++)
#pragma unroll
            for (int q = 0; q < 4; q++) accH[i][j][q] = 0.f;
    gemm_k128(accH, sb + XA_HI, sb + XA_LO, sb + W_HI, sb + W_LO, lane, wm, wn);
    __syncthreads();
    copy_w(sm, 4, tid);
    __syncthreads();
    gemm_k128(accH, sb + XS_HI, sb + XS_LO, sb + W_HI, sb + W_LO, lane, wm, wn);

    // GRU epilogue
    float* out = outp ? outp : g_state;
#pragma unroll
    for (int tm = 0; tm < 2; tm++)
#pragma unroll
        for (int tn = 0; tn < 8; tn++) {
            int col = wn * 64 + tn * 8 + (lane & 3) * 2;
            float2 bzv = *(const float2*)(bz + col);
            float2 bhv = *(const float2*)(bh + col);
#pragma unroll
            for (int h2 = 0; h2 < 2; h2++) {
                int r = row0 + wm * 32 + tm * 16 + (lane >> 2) + h2 * 8;
                if (r < NN) {
                    float2 s = *(const float2*)(g_state + (size_t)r * D + col);
                    float zp0 = accZ[tm][tn][h2 * 2]     + bzv.x;
                    float zp1 = accZ[tm][tn][h2 * 2 + 1] + bzv.y;
                    float z0 = 1.f / (1.f + expf(-zp0));
                    float z1 = 1.f / (1.f + expf(-zp1));
                    float c0 = tanhf(accH[tm][tn][h2 * 2]     + bhv.x);
                    float c1 = tanhf(accH[tm][tn][h2 * 2 + 1] + bhv.y);
                    float2 o;
                    o.x = (1.f - z0) * s.x + z0 * c0;
                    o.y = (1.f - z1) * s.y + z1 * c1;
                    *(float2*)(out + (size_t)r * D + col) = o;
                }
            }
        }
}

// ---------------------------------------------------------------------------
extern "C" void kernel_launch(void* const* d_in, const int* in_sizes, int n_in,
                              void* d_out, int out_size) {
    const int*   ei       = (const int*)d_in[0];
    const int*   src      = ei;
    const int*   dst      = ei + NE;
    const int*   etype    = (const int*)d_in[1];
    const int*   etime    = (const int*)d_in[2];
    const float* ew       = (const float*)d_in[3];
    const float* node_emb = (const float*)d_in[4];
    const float* rel_emb  = (const float*)d_in[5];
    const float* Wenc     = (const float*)d_in[6];
    const float* Wz       = (const float*)d_in[7];
    const float* Uz       = (const float*)d_in[8];
    const float* Wh       = (const float*)d_in[9];
    const float* Uh       = (const float*)d_in[10];
    const float* bz       = (const float*)d_in[11];
    const float* bh       = (const float*)d_in[12];

    cudaFuncSetAttribute(step_kernel, cudaFuncAttributeMaxDynamicSharedMemorySize, SMEM_BYTES);

    zero_kernel<<<2048, 256>>>();
    prep_weights<<<(5 * 128 * 128 + 255) / 256, 256>>>(Wenc, Wz, Uz, Wh, Uh);
    scatter_kernel<<<(NE * 32 + 255) / 256, 256>>>(src, dst, etype, etime, ew,
                                                   node_emb, rel_emb);

    for (int t = 0; t < NT; t++) {
        step_kernel<<<NTILES, 256, SMEM_BYTES>>>(t, bz, bh,
                                                 (t == NT - 1) ? (float*)d_out : nullptr);
    }
}